// round 8
// baseline (speedup 1.0000x reference)
#include <cuda_runtime.h>
#include <cuda_fp16.h>
#include <cstdint>

#define Nn 32768
#define Dd 256
#define Kk 8192

#define BM 128
#define BN 128
#define BK 64
#define NCHUNK (Kk / BN)        // 64
#define NIT (NCHUNK * 4)        // 256 iterations (4 x 64-dim slabs per chunk)
#define CAP 8192u
#define MARGIN 0.1f
#define KSPLIT 8

// ---------------------------------------------------------------------------
// Device scratch
// ---------------------------------------------------------------------------
__device__ __half g_xh[Nn * Dd];
__device__ __half g_wh[Kk * Dd];
__device__ float g_wn[Kk];
__device__ int g_idx[Nn];
__device__ unsigned int g_flag[CAP];
__device__ unsigned int g_nflag;
__device__ unsigned long long g_res[Nn];

// ---------------------------------------------------------------------------
__device__ __forceinline__ uint32_t smem_to_u32(const void* p) {
    uint32_t a;
    asm("{ .reg .u64 t; cvta.to.shared.u64 t, %1; cvt.u32.u64 %0, t; }"
        : "=r"(a) : "l"(p));
    return a;
}

__device__ __forceinline__ void cpasync16(uint32_t dst, const void* src) {
    asm volatile("cp.async.cg.shared.global [%0], [%1], 16;" :: "r"(dst), "l"(src));
}

#define CP_COMMIT() asm volatile("cp.async.commit_group;" ::: "memory")
#define CP_WAIT0()  asm volatile("cp.async.wait_group 0;" ::: "memory")

#define LDSM_X4(r0, r1, r2, r3, addr) \
    asm volatile("ldmatrix.sync.aligned.m8n8.x4.shared.b16 {%0,%1,%2,%3}, [%4];" \
        : "=r"(r0), "=r"(r1), "=r"(r2), "=r"(r3) : "r"(addr))

#define MMA16816(c, a, b) \
    asm volatile("mma.sync.aligned.m16n8k16.row.col.f32.f16.f16.f32 " \
        "{%0,%1,%2,%3}, {%4,%5,%6,%7}, {%8,%9}, {%0,%1,%2,%3};" \
        : "+f"((c)[0]), "+f"((c)[1]), "+f"((c)[2]), "+f"((c)[3]) \
        : "r"((a)[0]), "r"((a)[1]), "r"((a)[2]), "r"((a)[3]), \
          "r"((b)[0]), "r"((b)[1]))

// SMEM layout (stage1, dynamic), 144B row pitch (odd multiple of 16B):
//  2 stages x (A 128x144 + B 128x144) = 2 x 36864 = 73728
//  wns[2][128] = 1024 ; merge mv1/mv2/mi = 3 x 4096
#define SM_STAGE  36864
#define ATILE 0
#define BTILE 18432
#define SM_WNS    73728
#define SM_MV1    74752
#define SM_MV2    78848
#define SM_MI     82944
#define SMEM_TOTAL 87040

// ---------------------------------------------------------------------------
// Preprocessing: fp32 -> fp16
// ---------------------------------------------------------------------------
__global__ void convx_kernel(const float* __restrict__ X) {
    int i = blockIdx.x * 256 + threadIdx.x;
    if (i == 0) g_nflag = 0;
    if (i < Nn * Dd / 2) {
        float2 v = ((const float2*)X)[i];
        ((__half2*)g_xh)[i] = __halves2half2(__float2half(v.x), __float2half(v.y));
    }
}

__global__ void convw_kernel(const float* __restrict__ W) {
    int i = blockIdx.x * 256 + threadIdx.x;
    if (i < Kk * Dd / 2) {
        float2 v = ((const float2*)W)[i];
        ((__half2*)g_wh)[i] = __halves2half2(__float2half(v.x), __float2half(v.y));
    }
}

__global__ void wnorm_kernel(const float* __restrict__ W) {
    int k = blockIdx.x * 8 + (threadIdx.x >> 5);
    int lane = threadIdx.x & 31;
    const float4* wp = (const float4*)(W + (size_t)k * Dd);
    float4 a = wp[lane * 2];
    float4 b = wp[lane * 2 + 1];
    float s = a.x * a.x + a.y * a.y + a.z * a.z + a.w * a.w
            + b.x * b.x + b.y * b.y + b.z * b.z + b.w * b.w;
    #pragma unroll
    for (int o = 16; o > 0; o >>= 1) s += __shfl_xor_sync(0xffffffffu, s, o);
    if (lane == 0) g_wn[k] = 0.5f * s;
}

// ---------------------------------------------------------------------------
// Stage 1: fp16 warp-MMA GEMM, BK=64 double-buffered, 2 CTAs/SM
// Per iter: WAIT0 -> sync -> prefetch(commit) -> 64 MMAs/warp
// ---------------------------------------------------------------------------
__global__ void __launch_bounds__(256, 2) stage1_kernel() {
    extern __shared__ char smem[];
    const uint32_t sbase = smem_to_u32(smem);
    float* wnsS = (float*)(smem + SM_WNS);
    float* mv1 = (float*)(smem + SM_MV1);
    float* mv2 = (float*)(smem + SM_MV2);
    int*   mi  = (int*)(smem + SM_MI);

    const int tid = threadIdx.x;
    const int lane = tid & 31;
    const int wid = tid >> 5;
    const int warp_m = wid & 3;        // 4 warps x 32 rows
    const int warp_n = wid >> 2;       // 2 warps x 64 cols
    const int row0 = blockIdx.x * BM;

    const uint32_t aBase = sbase + ATILE +
        (uint32_t)((warp_m * 32 + (lane & 15)) * 144 + (lane >> 4) * 16);
    const uint32_t bBase = sbase + BTILE +
        (uint32_t)((warp_n * 64 + (lane & 7) + ((lane >> 4) & 1) * 8) * 144 +
                   ((lane >> 3) & 1) * 16);

    // per-iter loads: A 16KB + B 16KB; thread covers row tid>>1, chunks (tid&1)*4+q
    const int ldRow = tid >> 1;
    const int ldC0 = (tid & 1) * 4;

    // prologue: stage 0 = (ch 0, kt 0); wns(ch0)
    #pragma unroll
    for (int q = 0; q < 4; q++) {
        int c = ldC0 + q;
        cpasync16(sbase + ATILE + (uint32_t)(ldRow * 144 + c * 16),
                  g_xh + (size_t)(row0 + ldRow) * Dd + c * 8);
        cpasync16(sbase + BTILE + (uint32_t)(ldRow * 144 + c * 16),
                  g_wh + (size_t)ldRow * Dd + c * 8);
    }
    CP_COMMIT();
    if (tid < BN) wnsS[tid] = g_wn[tid];

    float best1[4], best2[4];
    int idx1[4];
    #pragma unroll
    for (int r = 0; r < 4; r++) { best1[r] = -3.4e38f; best2[r] = -3.4e38f; idx1[r] = 0; }

    float acc[2][8][4];

    for (int it = 0; it < NIT; it++) {
        const int ch = it >> 2;
        const int kt = it & 3;

        CP_WAIT0();          // drain the group filling stage it&1
        __syncthreads();     // all warps done with previous compute + data visible

        // prefetch iter it+1 into the other stage (wrap at tail: harmless dummy)
        {
            const int nit = (it + 1) & (NIT - 1);
            const int nch = nit >> 2;
            const int nkt = nit & 3;
            const uint32_t st = sbase + (uint32_t)((~it & 1) * SM_STAGE);
            #pragma unroll
            for (int q = 0; q < 4; q++) {
                int c = ldC0 + q;
                cpasync16(st + ATILE + (uint32_t)(ldRow * 144 + c * 16),
                          g_xh + (size_t)(row0 + ldRow) * Dd + nkt * BK + c * 8);
                cpasync16(st + BTILE + (uint32_t)(ldRow * 144 + c * 16),
                          g_wh + (size_t)(nch * BN + ldRow) * Dd + nkt * BK + c * 8);
            }
            CP_COMMIT();
        }

        if (kt == 0) {
            #pragma unroll
            for (int i = 0; i < 2; i++)
                #pragma unroll
                for (int j = 0; j < 8; j++)
                    #pragma unroll
                    for (int q = 0; q < 4; q++) acc[i][j][q] = 0.0f;
            if (ch + 1 < NCHUNK && tid < BN)
                wnsS[((ch + 1) & 1) * BN + tid] = g_wn[(ch + 1) * BN + tid];
        }

        // compute: 4 k16-steps on this 64-dim slab
        const uint32_t so = (uint32_t)((it & 1) * SM_STAGE);
        #pragma unroll
        for (int ks = 0; ks < 4; ks++) {
            uint32_t a[2][4];
            #pragma unroll
            for (int i = 0; i < 2; i++)
                LDSM_X4(a[i][0], a[i][1], a[i][2], a[i][3],
                        aBase + so + (uint32_t)(i * 2304 + ks * 32));
            uint32_t b[8][2];
            #pragma unroll
            for (int jp = 0; jp < 4; jp++)
                LDSM_X4(b[2 * jp][0], b[2 * jp][1], b[2 * jp + 1][0], b[2 * jp + 1][1],
                        bBase + so + (uint32_t)(jp * 2304 + ks * 32));
            #pragma unroll
            for (int i = 0; i < 2; i++)
                #pragma unroll
                for (int j = 0; j < 8; j++)
                    MMA16816(acc[i][j], a[i], b[j]);
        }

        // fused top-2 argmax at chunk end
        if (kt == 3) {
            const int kc = ch * BN;
            const float* wn = wnsS + (ch & 1) * BN;
            #pragma unroll
            for (int i = 0; i < 2; i++) {
                #pragma unroll
                for (int h = 0; h < 2; h++) {
                    const int r = i * 2 + h;
                    #pragma unroll
                    for (int j = 0; j < 8; j++) {
                        int col = warp_n * 64 + j * 8 + (lane & 3) * 2;
                        #pragma unroll
                        for (int q = 0; q < 2; q++) {
                            float s = acc[i][j][h * 2 + q] - wn[col + q];
                            int k = kc + col + q;
                            if (s > best1[r]) { best2[r] = best1[r]; best1[r] = s; idx1[r] = k; }
                            else if (s > best2[r]) { best2[r] = s; }
                        }
                    }
                }
            }
        }
    }

    // cross-thread merge: 8 entries per row
    const int e = warp_n * 4 + (lane & 3);
    #pragma unroll
    for (int r = 0; r < 4; r++) {
        int row = warp_m * 32 + (r >> 1) * 16 + (lane >> 2) + (r & 1) * 8;
        mv1[row * 8 + e] = best1[r];
        mv2[row * 8 + e] = best2[r];
        mi[row * 8 + e] = idx1[r];
    }
    __syncthreads();

    if (tid < BM) {
        float b1 = -3.4e38f, b2 = -3.4e38f;
        int bi = 0;
        #pragma unroll
        for (int t = 0; t < 8; t++) {
            float v = mv1[tid * 8 + t];
            int ii = mi[tid * 8 + t];
            if (v > b1 || (v == b1 && ii < bi)) { b2 = (b2 > b1) ? b2 : b1; b1 = v; bi = ii; }
            else if (v > b2) b2 = v;
            float v2 = mv2[tid * 8 + t];
            if (v2 > b2) b2 = v2;
        }
        int n = row0 + tid;
        g_idx[n] = bi;
        if (b1 - b2 < MARGIN) {
            unsigned slot = atomicAdd(&g_nflag, 1u);
            if (slot < CAP) {
                g_res[n] = 0ull;
                __threadfence();
                g_flag[slot] = n;
            }
        }
    }
}

// ---------------------------------------------------------------------------
// Batched rescue: 32 flagged rows per block x 1024-codeword K-split.
// Exact fp32 rescore; combine via packed atomicMax. DYNAMIC smem.
// ---------------------------------------------------------------------------
#define WPITCH 260   // floats per padded W row in smem
#define RS_XS 0
#define RS_WS (32 * 256 * 4)
#define RS_SMEM (RS_WS + 32 * WPITCH * 4)   // 66048 bytes

__global__ void __launch_bounds__(256) rescue_kernel(const float* __restrict__ X,
                                                    const float* __restrict__ W) {
    extern __shared__ char rsm[];
    float* xs = (float*)(rsm + RS_XS);          // [32][256]
    float* ws = (float*)(rsm + RS_WS);          // [32 * WPITCH]

    unsigned cnt = g_nflag; if (cnt > CAP) cnt = CAP;
    const unsigned grp = blockIdx.x >> 3;          // row group (32 rows)
    const int ksp = blockIdx.x & 7;                // k range [ksp*1024, +1024)
    if (grp * 32 >= cnt) return;

    const int tid = threadIdx.x;
    const int ty = tid >> 5;                       // warp id: owns rows ty*4..ty*4+3
    const int tx = tid & 31;

    // load 32 X rows (row = tid>>3, 8 float4 per thread)
    {
        const int r = tid >> 3, seg = tid & 7;
        unsigned slot = grp * 32 + r;
        int n = (int)g_flag[slot < cnt ? slot : (grp * 32)];
        const float4* src = (const float4*)(X + (size_t)n * Dd);
        #pragma unroll
        for (int q = 0; q < 8; q++)
            *(float4*)&xs[r * 256 + (seg * 8 + q) * 4] = src[seg * 8 + q];
    }

    unsigned long long key[4];
    #pragma unroll
    for (int i = 0; i < 4; i++) key[i] = 0ull;

    const int k0 = ksp * (Kk / KSPLIT);
    for (int kc = 0; kc < Kk / KSPLIT; kc += 32) {
        __syncthreads();
        // stage 32 codewords
        {
            const int kr = tid >> 3, seg = tid & 7;
            const float4* src = (const float4*)(W + (size_t)(k0 + kc + kr) * Dd);
            #pragma unroll
            for (int q = 0; q < 8; q++)
                *(float4*)&ws[kr * WPITCH + (seg * 8 + q) * 4] = src[seg * 8 + q];
        }
        __syncthreads();

        const int k = k0 + kc + tx;
        float dot[4];
        #pragma unroll
        for (int i = 0; i < 4; i++) dot[i] = 0.0f;
        #pragma unroll
        for (int d = 0; d < 256; d += 4) {
            float4 wv = *(const float4*)&ws[tx * WPITCH + d];
            #pragma unroll
            for (int i = 0; i < 4; i++) {
                float4 xv = *(const float4*)&xs[(ty * 4 + i) * 256 + d];
                dot[i] += wv.x * xv.x + wv.y * xv.y + wv.z * xv.z + wv.w * xv.w;
            }
        }
        const float wn = g_wn[k];
        #pragma unroll
        for (int i = 0; i < 4; i++) {
            float s = dot[i] - wn;
            unsigned u = __float_as_uint(s);
            u = (u & 0x80000000u) ? ~u : (u | 0x80000000u);
            unsigned long long kk2 =
                ((unsigned long long)u << 32) | (unsigned long long)(0xFFFFFFFFu - (unsigned)k);
            if (kk2 > key[i]) key[i] = kk2;
        }
    }

    // warp-reduce max per row, then atomicMax
    #pragma unroll
    for (int i = 0; i < 4; i++) {
        unsigned long long kv = key[i];
        #pragma unroll
        for (int o = 16; o > 0; o >>= 1) {
            unsigned long long other = __shfl_xor_sync(0xffffffffu, kv, o);
            if (other > kv) kv = other;
        }
        if (tx == 0) {
            unsigned slot = grp * 32 + ty * 4 + i;
            if (slot < cnt) atomicMax(&g_res[g_flag[slot]], kv);
        }
    }
}

__global__ void apply_kernel() {
    unsigned cnt = g_nflag; if (cnt > CAP) cnt = CAP;
    unsigned t = blockIdx.x * 256 + threadIdx.x;
    if (t < cnt) {
        int n = (int)g_flag[t];
        unsigned long long key = g_res[n];
        g_idx[n] = (int)(0xFFFFFFFFu - (unsigned)(key & 0xFFFFFFFFull));
    }
}

// ---------------------------------------------------------------------------
__global__ void gather_kernel(const float* __restrict__ W,
                              float* __restrict__ outq,
                              float* __restrict__ outi,
                              int write_idx) {
    int n = blockIdx.x;
    int idx = g_idx[n];
    const float4* src = (const float4*)(W + (size_t)idx * Dd);
    float4* dst = (float4*)(outq + (size_t)n * Dd);
    dst[threadIdx.x] = src[threadIdx.x];
    if (threadIdx.x == 0 && write_idx) outi[n] = (float)idx;
}

// ---------------------------------------------------------------------------
extern "C" void kernel_launch(void* const* d_in, const int* in_sizes, int n_in,
                              void* d_out, int out_size) {
    const float* X = (const float*)d_in[0];
    const float* W = (const float*)d_in[1];
    float* out = (float*)d_out;

    cudaFuncSetAttribute(stage1_kernel,
                         cudaFuncAttributeMaxDynamicSharedMemorySize, SMEM_TOTAL);
    cudaFuncSetAttribute(rescue_kernel,
                         cudaFuncAttributeMaxDynamicSharedMemorySize, RS_SMEM);

    convx_kernel<<<(Nn * Dd / 2 + 255) / 256, 256>>>(X);
    convw_kernel<<<(Kk * Dd / 2 + 255) / 256, 256>>>(W);
    wnorm_kernel<<<Kk / 8, 256>>>(W);

    stage1_kernel<<<Nn / BM, 256, SMEM_TOTAL>>>();

    rescue_kernel<<<(CAP / 32) * KSPLIT, 256, RS_SMEM>>>(X, W);
    apply_kernel<<<(CAP + 255) / 256, 256>>>();

    int write_idx = (out_size >= Nn * Dd + Nn) ? 1 : 0;
    gather_kernel<<<Nn, 64>>>(W, out, out + (size_t)Nn * Dd, write_idx);
}

// round 9
// speedup vs baseline: 1.1392x; 1.1392x over previous
#include <cuda_runtime.h>
#include <cuda_fp16.h>
#include <cstdint>

#define Nn 32768
#define Dd 256
#define Kk 8192

#define BM 128
#define BN 128
#define BK 32
#define NCHUNK (Kk / BN)        // 64
#define NIT (NCHUNK * 8)        // 512 iterations (8 x 32-dim slabs per chunk)
#define NSTAGE 5
#define CAP 8192u
#define MARGIN 0.05f
#define KSPLIT 8

// ---------------------------------------------------------------------------
// Device scratch
// ---------------------------------------------------------------------------
__device__ __half g_xh[Nn * Dd];
__device__ __half g_wh[Kk * Dd];
__device__ float g_wn[Kk];
__device__ int g_idx[Nn];
__device__ unsigned int g_flag[CAP];
__device__ unsigned int g_nflag;
__device__ unsigned long long g_res[Nn];

// ---------------------------------------------------------------------------
__device__ __forceinline__ uint32_t smem_to_u32(const void* p) {
    uint32_t a;
    asm("{ .reg .u64 t; cvta.to.shared.u64 t, %1; cvt.u32.u64 %0, t; }"
        : "=r"(a) : "l"(p));
    return a;
}

__device__ __forceinline__ void cpasync16(uint32_t dst, const void* src) {
    asm volatile("cp.async.cg.shared.global [%0], [%1], 16;" :: "r"(dst), "l"(src));
}

#define CP_COMMIT() asm volatile("cp.async.commit_group;" ::: "memory")
#define CP_WAIT3()  asm volatile("cp.async.wait_group 3;" ::: "memory")

#define LDSM_X4(r0, r1, r2, r3, addr) \
    asm volatile("ldmatrix.sync.aligned.m8n8.x4.shared.b16 {%0,%1,%2,%3}, [%4];" \
        : "=r"(r0), "=r"(r1), "=r"(r2), "=r"(r3) : "r"(addr))

#define MMA16816(c, a, b) \
    asm volatile("mma.sync.aligned.m16n8k16.row.col.f32.f16.f16.f32 " \
        "{%0,%1,%2,%3}, {%4,%5,%6,%7}, {%8,%9}, {%0,%1,%2,%3};" \
        : "+f"((c)[0]), "+f"((c)[1]), "+f"((c)[2]), "+f"((c)[3]) \
        : "r"((a)[0]), "r"((a)[1]), "r"((a)[2]), "r"((a)[3]), \
          "r"((b)[0]), "r"((b)[1]))

// SMEM layout (stage1, dynamic), 80B row pitch:
//  5 pipeline stages x (A 128x80 + B 128x80) = 5 x 20480 = 102400
//  wns[2][128] = 1024 ; merge mv1/mv2/mi = 3 x 4096
#define SM_STAGE  20480
#define ATILE 0
#define BTILE 10240
#define SM_WNS    102400
#define SM_MV1    103424
#define SM_MV2    107520
#define SM_MI     111616
#define SMEM_TOTAL 115712

// ---------------------------------------------------------------------------
// Preprocessing: fp32 -> fp16
// ---------------------------------------------------------------------------
__global__ void convx_kernel(const float* __restrict__ X) {
    int i = blockIdx.x * 256 + threadIdx.x;
    if (i == 0) g_nflag = 0;
    if (i < Nn * Dd / 2) {
        float2 v = ((const float2*)X)[i];
        ((__half2*)g_xh)[i] = __halves2half2(__float2half(v.x), __float2half(v.y));
    }
}

__global__ void convw_kernel(const float* __restrict__ W) {
    int i = blockIdx.x * 256 + threadIdx.x;
    if (i < Kk * Dd / 2) {
        float2 v = ((const float2*)W)[i];
        ((__half2*)g_wh)[i] = __halves2half2(__float2half(v.x), __float2half(v.y));
    }
}

__global__ void wnorm_kernel(const float* __restrict__ W) {
    int k = blockIdx.x * 8 + (threadIdx.x >> 5);
    int lane = threadIdx.x & 31;
    const float4* wp = (const float4*)(W + (size_t)k * Dd);
    float4 a = wp[lane * 2];
    float4 b = wp[lane * 2 + 1];
    float s = a.x * a.x + a.y * a.y + a.z * a.z + a.w * a.w
            + b.x * b.x + b.y * b.y + b.z * b.z + b.w * b.w;
    #pragma unroll
    for (int o = 16; o > 0; o >>= 1) s += __shfl_xor_sync(0xffffffffu, s, o);
    if (lane == 0) g_wn[k] = 0.5f * s;
}

// ---------------------------------------------------------------------------
// Stage 1: fp16 warp-MMA GEMM, 5-stage cp.async pipeline, 2 CTAs/SM
// ---------------------------------------------------------------------------
__global__ void __launch_bounds__(256, 2) stage1_kernel() {
    extern __shared__ char smem[];
    const uint32_t sbase = smem_to_u32(smem);
    float* wnsS = (float*)(smem + SM_WNS);
    float* mv1 = (float*)(smem + SM_MV1);
    float* mv2 = (float*)(smem + SM_MV2);
    int*   mi  = (int*)(smem + SM_MI);

    const int tid = threadIdx.x;
    const int lane = tid & 31;
    const int wid = tid >> 5;
    const int warp_m = wid & 3;        // 4 warps x 32 rows
    const int warp_n = wid >> 2;       // 2 warps x 64 cols
    const int row0 = blockIdx.x * BM;

    const uint32_t aBase = sbase + ATILE +
        (uint32_t)((warp_m * 32 + (lane & 15)) * 80 + (lane >> 4) * 16);
    const uint32_t bBase = sbase + BTILE +
        (uint32_t)((warp_n * 64 + (lane & 7) + ((lane >> 4) & 1) * 8) * 80 +
                   ((lane >> 3) & 1) * 16);

    // per-iter loads: A 8KB + B 8KB; thread covers row tid>>1, chunks (tid&1)*2+q
    const int ldRow = tid >> 1;
    const int ldC0 = (tid & 1) * 2;

    // prologue: fill 4 stages (iters 0..3 = ch0, kt 0..3) + wns(ch0)
    #pragma unroll
    for (int p = 0; p < 4; p++) {
        const uint32_t st = sbase + (uint32_t)(p * SM_STAGE);
        #pragma unroll
        for (int q = 0; q < 2; q++) {
            int c = ldC0 + q;
            cpasync16(st + ATILE + (uint32_t)(ldRow * 80 + c * 16),
                      g_xh + (size_t)(row0 + ldRow) * Dd + p * BK + c * 8);
            cpasync16(st + BTILE + (uint32_t)(ldRow * 80 + c * 16),
                      g_wh + (size_t)ldRow * Dd + p * BK + c * 8);
        }
        CP_COMMIT();
    }
    if (tid < BN) wnsS[tid] = g_wn[tid];

    float best1[4], best2[4];
    int idx1[4];
    #pragma unroll
    for (int r = 0; r < 4; r++) { best1[r] = -3.4e38f; best2[r] = -3.4e38f; idx1[r] = 0; }

    float acc[2][8][4];

    int cur = 0;        // stage holding iter 'it'
    int fill = 4;       // stage to fill with iter 'it+4'

    for (int it = 0; it < NIT; it++) {
        const int ch = it >> 3;
        const int kt = it & 7;

        CP_WAIT3();
        __syncthreads();

        // prefetch iter it+4 into stage 'fill' (wrap at tail: harmless dummy)
        {
            int nit = it + 4; if (nit >= NIT) nit -= NIT;
            const int nch = nit >> 3;
            const int nkt = nit & 7;
            const uint32_t st = sbase + (uint32_t)(fill * SM_STAGE);
            #pragma unroll
            for (int q = 0; q < 2; q++) {
                int c = ldC0 + q;
                cpasync16(st + ATILE + (uint32_t)(ldRow * 80 + c * 16),
                          g_xh + (size_t)(row0 + ldRow) * Dd + nkt * BK + c * 8);
                cpasync16(st + BTILE + (uint32_t)(ldRow * 80 + c * 16),
                          g_wh + (size_t)(nch * BN + ldRow) * Dd + nkt * BK + c * 8);
            }
            CP_COMMIT();
        }

        if (kt == 0) {
            #pragma unroll
            for (int i = 0; i < 2; i++)
                #pragma unroll
                for (int j = 0; j < 8; j++)
                    #pragma unroll
                    for (int q = 0; q < 4; q++) acc[i][j][q] = 0.0f;
            if (ch + 1 < NCHUNK && tid < BN)
                wnsS[((ch + 1) & 1) * BN + tid] = g_wn[(ch + 1) * BN + tid];
        }

        // compute: 2 k16-steps on this 32-dim slab
        const uint32_t so = (uint32_t)(cur * SM_STAGE);
        #pragma unroll
        for (int ks = 0; ks < 2; ks++) {
            uint32_t a[2][4];
            #pragma unroll
            for (int i = 0; i < 2; i++)
                LDSM_X4(a[i][0], a[i][1], a[i][2], a[i][3],
                        aBase + so + (uint32_t)(i * 1280 + ks * 32));
            uint32_t b[8][2];
            #pragma unroll
            for (int jp = 0; jp < 4; jp++)
                LDSM_X4(b[2 * jp][0], b[2 * jp][1], b[2 * jp + 1][0], b[2 * jp + 1][1],
                        bBase + so + (uint32_t)(jp * 1280 + ks * 32));
            #pragma unroll
            for (int i = 0; i < 2; i++)
                #pragma unroll
                for (int j = 0; j < 8; j++)
                    MMA16816(acc[i][j], a[i], b[j]);
        }

        if (++cur == NSTAGE) cur = 0;
        if (++fill == NSTAGE) fill = 0;

        // fused top-2 argmax at chunk end
        if (kt == 7) {
            const int kc = ch * BN;
            const float* wn = wnsS + (ch & 1) * BN;
            #pragma unroll
            for (int i = 0; i < 2; i++) {
                #pragma unroll
                for (int h = 0; h < 2; h++) {
                    const int r = i * 2 + h;
                    #pragma unroll
                    for (int j = 0; j < 8; j++) {
                        int col = warp_n * 64 + j * 8 + (lane & 3) * 2;
                        #pragma unroll
                        for (int q = 0; q < 2; q++) {
                            float s = acc[i][j][h * 2 + q] - wn[col + q];
                            int k = kc + col + q;
                            if (s > best1[r]) { best2[r] = best1[r]; best1[r] = s; idx1[r] = k; }
                            else if (s > best2[r]) { best2[r] = s; }
                        }
                    }
                }
            }
        }
    }

    // cross-thread merge: 8 entries per row
    const int e = warp_n * 4 + (lane & 3);
    #pragma unroll
    for (int r = 0; r < 4; r++) {
        int row = warp_m * 32 + (r >> 1) * 16 + (lane >> 2) + (r & 1) * 8;
        mv1[row * 8 + e] = best1[r];
        mv2[row * 8 + e] = best2[r];
        mi[row * 8 + e] = idx1[r];
    }
    __syncthreads();

    if (tid < BM) {
        float b1 = -3.4e38f, b2 = -3.4e38f;
        int bi = 0;
        #pragma unroll
        for (int t = 0; t < 8; t++) {
            float v = mv1[tid * 8 + t];
            int ii = mi[tid * 8 + t];
            if (v > b1 || (v == b1 && ii < bi)) { b2 = (b2 > b1) ? b2 : b1; b1 = v; bi = ii; }
            else if (v > b2) b2 = v;
            float v2 = mv2[tid * 8 + t];
            if (v2 > b2) b2 = v2;
        }
        int n = row0 + tid;
        g_idx[n] = bi;
        if (b1 - b2 < MARGIN) {
            unsigned slot = atomicAdd(&g_nflag, 1u);
            if (slot < CAP) {
                g_res[n] = 0ull;
                __threadfence();
                g_flag[slot] = n;
            }
        }
    }
}

// ---------------------------------------------------------------------------
// Batched rescue: 64 flagged rows per block x 1024-codeword K-split.
// 8 rows per thread (warp w owns rows w*8..w*8+7). Exact fp32; atomicMax.
// ---------------------------------------------------------------------------
#define WPITCH 260   // floats per padded W row in smem
#define RROWS 64
#define RS_XS 0
#define RS_WS (RROWS * 256 * 4)                 // 65536
#define RS_SMEM (RS_WS + 32 * WPITCH * 4)       // 98816 bytes

__global__ void __launch_bounds__(256) rescue_kernel(const float* __restrict__ X,
                                                    const float* __restrict__ W) {
    extern __shared__ char rsm[];
    float* xs = (float*)(rsm + RS_XS);          // [64][256]
    float* ws = (float*)(rsm + RS_WS);          // [32 * WPITCH]

    unsigned cnt = g_nflag; if (cnt > CAP) cnt = CAP;
    const unsigned grp = blockIdx.x >> 3;          // row group (64 rows)
    const int ksp = blockIdx.x & 7;                // k range [ksp*1024, +1024)
    if (grp * RROWS >= cnt) return;

    const int tid = threadIdx.x;
    const int w = tid >> 5;                        // warp: owns rows w*8..w*8+7
    const int tx = tid & 31;

    // load 64 X rows: 4096 float4, thread covers f = q*256 + tid
    #pragma unroll
    for (int q = 0; q < 16; q++) {
        int f = q * 256 + tid;
        int r = f >> 6, seg = f & 63;
        unsigned slot = grp * RROWS + r;
        int n = (int)g_flag[slot < cnt ? slot : (grp * RROWS)];
        *(float4*)&xs[r * 256 + seg * 4] =
            ((const float4*)(X + (size_t)n * Dd))[seg];
    }

    unsigned long long key[8];
    #pragma unroll
    for (int i = 0; i < 8; i++) key[i] = 0ull;

    const int k0 = ksp * (Kk / KSPLIT);
    for (int kc = 0; kc < Kk / KSPLIT; kc += 32) {
        __syncthreads();
        // stage 32 codewords
        {
            const int kr = tid >> 3, seg = tid & 7;
            const float4* src = (const float4*)(W + (size_t)(k0 + kc + kr) * Dd);
            #pragma unroll
            for (int q = 0; q < 8; q++)
                *(float4*)&ws[kr * WPITCH + (seg * 8 + q) * 4] = src[seg * 8 + q];
        }
        __syncthreads();

        const int k = k0 + kc + tx;
        float dot[8];
        #pragma unroll
        for (int i = 0; i < 8; i++) dot[i] = 0.0f;
        #pragma unroll
        for (int d = 0; d < 256; d += 4) {
            float4 wv = *(const float4*)&ws[tx * WPITCH + d];
            #pragma unroll
            for (int i = 0; i < 8; i++) {
                float4 xv = *(const float4*)&xs[(w * 8 + i) * 256 + d];
                dot[i] += wv.x * xv.x + wv.y * xv.y + wv.z * xv.z + wv.w * xv.w;
            }
        }
        const float wn = g_wn[k];
        #pragma unroll
        for (int i = 0; i < 8; i++) {
            float s = dot[i] - wn;
            unsigned u = __float_as_uint(s);
            u = (u & 0x80000000u) ? ~u : (u | 0x80000000u);
            unsigned long long kk2 =
                ((unsigned long long)u << 32) | (unsigned long long)(0xFFFFFFFFu - (unsigned)k);
            if (kk2 > key[i]) key[i] = kk2;
        }
    }

    // warp-reduce max per row, then atomicMax
    #pragma unroll
    for (int i = 0; i < 8; i++) {
        unsigned long long kv = key[i];
        #pragma unroll
        for (int o = 16; o > 0; o >>= 1) {
            unsigned long long other = __shfl_xor_sync(0xffffffffu, kv, o);
            if (other > kv) kv = other;
        }
        if (tx == 0) {
            unsigned slot = grp * RROWS + w * 8 + i;
            if (slot < cnt) atomicMax(&g_res[g_flag[slot]], kv);
        }
    }
}

__global__ void apply_kernel() {
    unsigned cnt = g_nflag; if (cnt > CAP) cnt = CAP;
    unsigned t = blockIdx.x * 256 + threadIdx.x;
    if (t < cnt) {
        int n = (int)g_flag[t];
        unsigned long long key = g_res[n];
        g_idx[n] = (int)(0xFFFFFFFFu - (unsigned)(key & 0xFFFFFFFFull));
    }
}

// ---------------------------------------------------------------------------
__global__ void gather_kernel(const float* __restrict__ W,
                              float* __restrict__ outq,
                              float* __restrict__ outi,
                              int write_idx) {
    int n = blockIdx.x;
    int idx = g_idx[n];
    const float4* src = (const float4*)(W + (size_t)idx * Dd);
    float4* dst = (float4*)(outq + (size_t)n * Dd);
    dst[threadIdx.x] = src[threadIdx.x];
    if (threadIdx.x == 0 && write_idx) outi[n] = (float)idx;
}

// ---------------------------------------------------------------------------
extern "C" void kernel_launch(void* const* d_in, const int* in_sizes, int n_in,
                              void* d_out, int out_size) {
    const float* X = (const float*)d_in[0];
    const float* W = (const float*)d_in[1];
    float* out = (float*)d_out;

    cudaFuncSetAttribute(stage1_kernel,
                         cudaFuncAttributeMaxDynamicSharedMemorySize, SMEM_TOTAL);
    cudaFuncSetAttribute(rescue_kernel,
                         cudaFuncAttributeMaxDynamicSharedMemorySize, RS_SMEM);

    convx_kernel<<<(Nn * Dd / 2 + 255) / 256, 256>>>(X);
    convw_kernel<<<(Kk * Dd / 2 + 255) / 256, 256>>>(W);
    wnorm_kernel<<<Kk / 8, 256>>>(W);

    stage1_kernel<<<Nn / BM, 256, SMEM_TOTAL>>>();

    rescue_kernel<<<(CAP / RROWS) * KSPLIT, 256, RS_SMEM>>>(X, W);
    apply_kernel<<<(CAP + 255) / 256, 256>>>();

    int write_idx = (out_size >= Nn * Dd + Nn) ? 1 : 0;
    gather_kernel<<<Nn, 64>>>(W, out, out + (size_t)Nn * Dd, write_idx);
}